// round 3
// baseline (speedup 1.0000x reference)
#include <cuda_runtime.h>
#include <cuda_bf16.h>
#include <cstdint>

#define HNUM 8
#define NSEQ 4096
#define FIN  512
#define HD   64

// ---------------- scratch (static device globals; no allocations) ----------
__device__ uint32_t g_XH[HNUM * NSEQ * (FIN / 2)];
__device__ uint32_t g_XL[HNUM * NSEQ * (FIN / 2)];
__device__ uint32_t g_WH[3 * HNUM * HD * (FIN / 2)];
__device__ uint32_t g_WL[3 * HNUM * HD * (FIN / 2)];
__device__ uint32_t g_WOH[FIN * (FIN / 2)];
__device__ uint32_t g_WOL[FIN * (FIN / 2)];
__device__ uint32_t g_QH[HNUM * NSEQ * (HD / 2)];
__device__ uint32_t g_QL[HNUM * NSEQ * (HD / 2)];
__device__ uint32_t g_KH[HNUM * NSEQ * (HD / 2)];
__device__ uint32_t g_KL[HNUM * NSEQ * (HD / 2)];
__device__ unsigned short g_VTH[HNUM * HD * NSEQ];
__device__ unsigned short g_VTL[HNUM * HD * NSEQ];
__device__ uint32_t g_HH[NSEQ * (FIN / 2)];
__device__ uint32_t g_HL[NSEQ * (FIN / 2)];
// bit-packed mask: bit j of word w = (mask[w*32+j] != 0), linear over [H,N,N]
__device__ uint32_t g_Mbits[HNUM * NSEQ * (NSEQ / 32)];

// ---------------- helpers --------------------------------------------------
__device__ __forceinline__ uint32_t pack_bf16x2(float lo_elem, float hi_elem) {
    return (uint32_t)__bfloat16_as_ushort(__float2bfloat16_rn(lo_elem)) |
           ((uint32_t)__bfloat16_as_ushort(__float2bfloat16_rn(hi_elem)) << 16);
}

__device__ __forceinline__ void split2(float a, float b, uint32_t& hi, uint32_t& lo) {
    float ah = __bfloat162float(__float2bfloat16_rn(a));
    float bh = __bfloat162float(__float2bfloat16_rn(b));
    hi = pack_bf16x2(a, b);
    lo = pack_bf16x2(a - ah, b - bh);
}

__device__ __forceinline__ void mma16816(float* c,
                                         uint32_t a0, uint32_t a1, uint32_t a2, uint32_t a3,
                                         uint32_t b0, uint32_t b1) {
    asm volatile(
        "mma.sync.aligned.m16n8k16.row.col.f32.bf16.bf16.f32 "
        "{%0,%1,%2,%3},{%4,%5,%6,%7},{%8,%9},{%0,%1,%2,%3};\n"
        : "+f"(c[0]), "+f"(c[1]), "+f"(c[2]), "+f"(c[3])
        : "r"(a0), "r"(a1), "r"(a2), "r"(a3), "r"(b0), "r"(b1));
}

__device__ __forceinline__ void cp16(uint32_t dst, const void* src) {
    asm volatile("cp.async.cg.shared.global [%0], [%1], 16;" :: "r"(dst), "l"(src));
}
__device__ __forceinline__ void cp_commit() {
    asm volatile("cp.async.commit_group;" ::: "memory");
}
__device__ __forceinline__ void cp_wait1() {
    asm volatile("cp.async.wait_group 1;" ::: "memory");
}

#define NEG_BIG (-1.0e30f)

// ---------------- mask bit-pack kernel -------------------------------------
__global__ void __launch_bounds__(256) mask_pack(const int* __restrict__ mask) {
    const int lane = threadIdx.x & 31;
    const size_t warp_global = (size_t)((blockIdx.x * blockDim.x + threadIdx.x) >> 5);
    const size_t base = warp_global * 1024;
    uint32_t word = 0;
#pragma unroll
    for (int i = 0; i < 32; i++) {
        int v = mask[base + (size_t)i * 32 + lane];
        uint32_t b = __ballot_sync(0xffffffffu, v != 0);
        if (lane == i) word = b;
    }
    g_Mbits[warp_global * 32 + lane] = word;
}

// ---------------- split kernel: fp32 -> packed bf16 hi/lo -------------------
__global__ void __launch_bounds__(256) split_kernel(const float* __restrict__ src,
                                                    int which, int nquads) {
    uint32_t* dH;
    uint32_t* dL;
    switch (which) {
        case 0: dH = g_XH;          dL = g_XL;          break;
        case 1: dH = g_WH;          dL = g_WL;          break;
        case 2: dH = g_WH + 131072; dL = g_WL + 131072; break;
        case 3: dH = g_WH + 262144; dL = g_WL + 262144; break;
        default: dH = g_WOH;        dL = g_WOL;         break;
    }
    for (int i = blockIdx.x * blockDim.x + threadIdx.x; i < nquads;
         i += gridDim.x * blockDim.x) {
        float4 v = reinterpret_cast<const float4*>(src)[i];
        uint32_t h0, l0, h1, l1;
        split2(v.x, v.y, h0, l0);
        split2(v.z, v.w, h1, l1);
        reinterpret_cast<uint2*>(dH)[i] = make_uint2(h0, h1);
        reinterpret_cast<uint2*>(dL)[i] = make_uint2(l0, l1);
    }
}

// ---------------- GEMM core: acc[128x64] += A[128,512] * B[64,512]^T --------
__device__ __forceinline__ void gemm_accum(const uint32_t* __restrict__ AHg,
                                           const uint32_t* __restrict__ ALg,
                                           const uint32_t* __restrict__ BHg,
                                           const uint32_t* __restrict__ BLg,
                                           float acc[8][4]) {
    __shared__ __align__(16) uint32_t AsH[128][36];
    __shared__ __align__(16) uint32_t AsL[128][36];
    __shared__ __align__(16) uint32_t BsH[64][36];
    __shared__ __align__(16) uint32_t BsL[64][36];

    const int tid = threadIdx.x;
    const int wid = tid >> 5, lane = tid & 31;
    const int g = lane >> 2, q = lane & 3;

    for (int kc = 0; kc < 256; kc += 32) {
#pragma unroll
        for (int j = 0; j < 4; j++) {
            int idx = tid + j * 256;
            int r = idx >> 3, c = (idx & 7) << 2;
            *reinterpret_cast<uint4*>(&AsH[r][c]) =
                *reinterpret_cast<const uint4*>(AHg + (size_t)r * 256 + kc + c);
            *reinterpret_cast<uint4*>(&AsL[r][c]) =
                *reinterpret_cast<const uint4*>(ALg + (size_t)r * 256 + kc + c);
        }
#pragma unroll
        for (int j = 0; j < 2; j++) {
            int idx = tid + j * 256;
            int r = idx >> 3, c = (idx & 7) << 2;
            *reinterpret_cast<uint4*>(&BsH[r][c]) =
                *reinterpret_cast<const uint4*>(BHg + (size_t)r * 256 + kc + c);
            *reinterpret_cast<uint4*>(&BsL[r][c]) =
                *reinterpret_cast<const uint4*>(BLg + (size_t)r * 256 + kc + c);
        }
        __syncthreads();
#pragma unroll
        for (int ks = 0; ks < 4; ks++) {
            const int ar = wid * 16 + g;
            const int wi = ks * 8 + q;
            uint32_t a0h = AsH[ar][wi],     a1h = AsH[ar + 8][wi];
            uint32_t a2h = AsH[ar][wi + 4], a3h = AsH[ar + 8][wi + 4];
            uint32_t a0l = AsL[ar][wi],     a1l = AsL[ar + 8][wi];
            uint32_t a2l = AsL[ar][wi + 4], a3l = AsL[ar + 8][wi + 4];
#pragma unroll
            for (int nt = 0; nt < 8; nt++) {
                const int br = nt * 8 + g;
                uint32_t b0h = BsH[br][wi], b1h = BsH[br][wi + 4];
                uint32_t b0l = BsL[br][wi], b1l = BsL[br][wi + 4];
                mma16816(acc[nt], a0h, a1h, a2h, a3h, b0h, b1h);
                mma16816(acc[nt], a0h, a1h, a2h, a3h, b0l, b1l);
                mma16816(acc[nt], a0l, a1l, a2l, a3l, b0h, b1h);
            }
        }
        __syncthreads();
    }
}

// ---------------- stage 1: QKV projections --------------------------------
__global__ void __launch_bounds__(256) qkv_kernel() {
    const int bm = blockIdx.x, h = blockIdx.y, z = blockIdx.z;
    const int tid = threadIdx.x;
    const int wid = tid >> 5, lane = tid & 31;
    const int g = lane >> 2, q = lane & 3;

    float acc[8][4];
#pragma unroll
    for (int i = 0; i < 8; i++)
#pragma unroll
        for (int j = 0; j < 4; j++) acc[i][j] = 0.f;

    const uint32_t* AH = g_XH + (size_t)(h * NSEQ + bm * 128) * 256;
    const uint32_t* AL = g_XL + (size_t)(h * NSEQ + bm * 128) * 256;
    const uint32_t* BH = g_WH + (size_t)((z * HNUM + h) * HD) * 256;
    const uint32_t* BL = g_WL + (size_t)((z * HNUM + h) * HD) * 256;
    gemm_accum(AH, AL, BH, BL, acc);

    const int r0 = wid * 16 + g;
    if (z < 2) {
        uint32_t* dH = (z == 0) ? g_QH : g_KH;
        uint32_t* dL = (z == 0) ? g_QL : g_KL;
        const size_t rb0 = (size_t)(h * NSEQ + bm * 128 + r0) * 32;
        const size_t rb1 = rb0 + 8 * 32;
#pragma unroll
        for (int nt = 0; nt < 8; nt++) {
            int w = nt * 4 + q;
            uint32_t H, L;
            split2(acc[nt][0], acc[nt][1], H, L);
            dH[rb0 + w] = H; dL[rb0 + w] = L;
            split2(acc[nt][2], acc[nt][3], H, L);
            dH[rb1 + w] = H; dL[rb1 + w] = L;
        }
    } else {
        const int n0 = bm * 128 + r0;
#pragma unroll
        for (int nt = 0; nt < 8; nt++) {
            int cx = nt * 8 + 2 * q;
#pragma unroll
            for (int e = 0; e < 2; e++) {
                size_t b0 = (size_t)(h * HD + cx + e) * NSEQ;
                float v0 = acc[nt][e], v1 = acc[nt][2 + e];
                float h0 = __bfloat162float(__float2bfloat16_rn(v0));
                float h1 = __bfloat162float(__float2bfloat16_rn(v1));
                g_VTH[b0 + n0]     = __bfloat16_as_ushort(__float2bfloat16_rn(v0));
                g_VTL[b0 + n0]     = __bfloat16_as_ushort(__float2bfloat16_rn(v0 - h0));
                g_VTH[b0 + n0 + 8] = __bfloat16_as_ushort(__float2bfloat16_rn(v1));
                g_VTL[b0 + n0 + 8] = __bfloat16_as_ushort(__float2bfloat16_rn(v1 - h1));
            }
        }
    }
}

// ---------------- stage 3: output projection ------------------------------
__global__ void __launch_bounds__(256) out_kernel(float* __restrict__ out) {
    const int bm = blockIdx.x, bn = blockIdx.y;
    const int tid = threadIdx.x;
    const int wid = tid >> 5, lane = tid & 31;
    const int g = lane >> 2, q = lane & 3;

    float acc[8][4];
#pragma unroll
    for (int i = 0; i < 8; i++)
#pragma unroll
        for (int j = 0; j < 4; j++) acc[i][j] = 0.f;

    gemm_accum(g_HH + (size_t)bm * 128 * 256, g_HL + (size_t)bm * 128 * 256,
               g_WOH + (size_t)bn * HD * 256, g_WOL + (size_t)bn * HD * 256, acc);

    const int r0 = wid * 16 + g;
#pragma unroll
    for (int nt = 0; nt < 8; nt++) {
        int cx = bn * HD + nt * 8 + 2 * q;
        *reinterpret_cast<float2*>(out + (size_t)(bm * 128 + r0) * FIN + cx) =
            make_float2(acc[nt][0], acc[nt][1]);
        *reinterpret_cast<float2*>(out + (size_t)(bm * 128 + r0 + 8) * FIN + cx) =
            make_float2(acc[nt][2], acc[nt][3]);
    }
}

// ---------------- stage 2: flash attention --------------------------------
// smem: K double-buffered (2 x 4608 words), V triple-buffered (3 x 4608 words)
// each K/V buffer: H at +0, L at +2304; row stride 36 words
#define KBUF_WORDS 4608
#define VBUF_WORDS 4608
#define KBUF(i) ((i) * KBUF_WORDS)
#define VBUF(i) (2 * KBUF_WORDS + (i) * VBUF_WORDS)
#define ATTN_SMEM_WORDS (2 * KBUF_WORDS + 3 * VBUF_WORDS)   // 23040 words = 92160 B

__device__ __forceinline__ void issue_tile(int h, int nb, uint32_t dK, uint32_t dV) {
    const int tid = threadIdx.x;
#pragma unroll
    for (int j = 0; j < 2; j++) {
        int chunk = tid + j * 256;
        int r = chunk >> 3, c = chunk & 7;
        const uint32_t* sKH = g_KH + (size_t)(h * NSEQ + nb * 64 + r) * 32 + c * 4;
        const uint32_t* sKL = g_KL + (size_t)(h * NSEQ + nb * 64 + r) * 32 + c * 4;
        const unsigned short* sVH = g_VTH + (size_t)(h * HD + r) * NSEQ + nb * 64 + c * 8;
        const unsigned short* sVL = g_VTL + (size_t)(h * HD + r) * NSEQ + nb * 64 + c * 8;
        uint32_t off = (uint32_t)(r * 36 + c * 4) * 4;
        cp16(dK + off, sKH);
        cp16(dK + off + 2304 * 4, sKL);
        cp16(dV + off, sVH);
        cp16(dV + off + 2304 * 4, sVL);
    }
}

__device__ __forceinline__ void pv_accum(float O[8][4],
                                         const uint32_t ph[4][4], const uint32_t pl[4][4],
                                         const uint32_t* __restrict__ VH,
                                         const uint32_t* __restrict__ VL,
                                         int g, int q) {
#pragma unroll
    for (int ks = 0; ks < 4; ks++) {
        const int wi = ks * 8 + q;
#pragma unroll
        for (int nt = 0; nt < 8; nt++) {
            const int vr = nt * 8 + g;
            uint32_t b0h = VH[vr * 36 + wi], b1h = VH[vr * 36 + wi + 4];
            uint32_t b0l = VL[vr * 36 + wi], b1l = VL[vr * 36 + wi + 4];
            mma16816(O[nt], ph[ks][0], ph[ks][1], ph[ks][2], ph[ks][3], b0h, b1h);
            mma16816(O[nt], ph[ks][0], ph[ks][1], ph[ks][2], ph[ks][3], b0l, b1l);
            mma16816(O[nt], pl[ks][0], pl[ks][1], pl[ks][2], pl[ks][3], b0h, b1h);
        }
    }
}

__global__ void __launch_bounds__(256) attn_kernel() {
    extern __shared__ __align__(16) uint32_t sm[];
    const uint32_t smem_u32 = (uint32_t)__cvta_generic_to_shared(sm);

    const int tid = threadIdx.x, wid = tid >> 5, lane = tid & 31;
    const int g = lane >> 2, q = lane & 3;
    const int bm = blockIdx.x, h = blockIdx.y;

    // ---- Q fragments into registers (once per CTA)
    uint32_t qh[4][4], ql[4][4];
    {
        const size_t rb0 = (size_t)(h * NSEQ + bm * 128 + wid * 16 + g) * 32;
        const size_t rb1 = rb0 + 8 * 32;
#pragma unroll
        for (int ks = 0; ks < 4; ks++) {
            int wi = ks * 8 + q;
            qh[ks][0] = g_QH[rb0 + wi];
            qh[ks][1] = g_QH[rb1 + wi];
            qh[ks][2] = g_QH[rb0 + wi + 4];
            qh[ks][3] = g_QH[rb1 + wi + 4];
            ql[ks][0] = g_QL[rb0 + wi];
            ql[ks][1] = g_QL[rb1 + wi];
            ql[ks][2] = g_QL[rb0 + wi + 4];
            ql[ks][3] = g_QL[rb1 + wi + 4];
        }
    }

    // bit-packed mask row pointers (128 words per row)
    const uint32_t* mrow0 = g_Mbits + (size_t)(h * NSEQ + bm * 128 + wid * 16 + g) * 128;
    const uint32_t* mrow1 = mrow0 + 8 * 128;

    float O[8][4];
#pragma unroll
    for (int i = 0; i < 8; i++)
#pragma unroll
        for (int j = 0; j < 4; j++) O[i][j] = 0.f;
    const float NEGINF = __int_as_float(0xff800000);
    float m0 = NEGINF, m1 = NEGINF, l0s = 0.f, l1s = 0.f;
    float alpha0 = 0.f, alpha1 = 0.f;   // O-rescale factor pending from previous iter
    uint32_t ph[4][4], pl[4][4];        // previous block's P fragments

    issue_tile(h, 0, smem_u32 + KBUF(0) * 4, smem_u32 + VBUF(0) * 4);
    cp_commit();
    issue_tile(h, 1, smem_u32 + KBUF(1) * 4, smem_u32 + VBUF(1) * 4);
    cp_commit();

    for (int nb = 0; nb < NSEQ / 64; nb++) {
        // mask bit words (issued early; consumed after S-mma)
        uint2 mw0 = *reinterpret_cast<const uint2*>(mrow0 + nb * 2);
        uint2 mw1 = *reinterpret_cast<const uint2*>(mrow1 + nb * 2);

        cp_wait1();        // tile nb landed
        __syncthreads();

        const uint32_t* KH = sm + KBUF(nb & 1);
        const uint32_t* KL = KH + 2304;

        // ---- S = Q * K^T (tensor)
        float S[8][4];
#pragma unroll
        for (int i = 0; i < 8; i++)
#pragma unroll
            for (int j = 0; j < 4; j++) S[i][j] = 0.f;
#pragma unroll
        for (int ks = 0; ks < 4; ks++) {
            const int wi = ks * 8 + q;
#pragma unroll
            for (int nt = 0; nt < 8; nt++) {
                const int br = nt * 8 + g;
                uint32_t b0h = KH[br * 36 + wi], b1h = KH[br * 36 + wi + 4];
                uint32_t b0l = KL[br * 36 + wi], b1l = KL[br * 36 + wi + 4];
                mma16816(S[nt], qh[ks][0], qh[ks][1], qh[ks][2], qh[ks][3], b0h, b1h);
                mma16816(S[nt], qh[ks][0], qh[ks][1], qh[ks][2], qh[ks][3], b0l, b1l);
                mma16816(S[nt], ql[ks][0], ql[ks][1], ql[ks][2], ql[ks][3], b0h, b1h);
            }
        }

        // ---- deferred PV of previous block (tensor) overlapped w/ softmax (ALU)
        if (nb > 0) {
            const uint32_t* VH = sm + VBUF((nb + 2) % 3);   // V(nb-1)
            const uint32_t* VL = VH + 2304;
#pragma unroll
            for (int nt = 0; nt < 8; nt++) {
                O[nt][0] *= alpha0;
                O[nt][1] *= alpha0;
                O[nt][2] *= alpha1;
                O[nt][3] *= alpha1;
            }
            pv_accum(O, ph, pl, VH, VL, g, q);
        }

        // ---- mask + scale (bit test)
#pragma unroll
        for (int nt = 0; nt < 8; nt++) {
            uint32_t w0 = (nt < 4) ? mw0.x : mw0.y;
            uint32_t w1 = (nt < 4) ? mw1.x : mw1.y;
            int s = (nt & 3) * 8 + 2 * q;
            uint32_t t0 = w0 >> s, t1 = w1 >> s;
            S[nt][0] = (t0 & 1) ? S[nt][0] * 0.125f : NEG_BIG;
            S[nt][1] = (t0 & 2) ? S[nt][1] * 0.125f : NEG_BIG;
            S[nt][2] = (t1 & 1) ? S[nt][2] * 0.125f : NEG_BIG;
            S[nt][3] = (t1 & 2) ? S[nt][3] * 0.125f : NEG_BIG;
        }

        // ---- online softmax
        float mx0 = S[0][0], mx1 = S[0][2];
#pragma unroll
        for (int nt = 0; nt < 8; nt++) {
            mx0 = fmaxf(mx0, fmaxf(S[nt][0], S[nt][1]));
            mx1 = fmaxf(mx1, fmaxf(S[nt][2], S[nt][3]));
        }
        mx0 = fmaxf(mx0, __shfl_xor_sync(0xffffffffu, mx0, 1));
        mx0 = fmaxf(mx0, __shfl_xor_sync(0xffffffffu, mx0, 2));
        mx1 = fmaxf(mx1, __shfl_xor_sync(0xffffffffu, mx1, 1));
        mx1 = fmaxf(mx1, __shfl_xor_sync(0xffffffffu, mx1, 2));

        float mn0 = fmaxf(m0, mx0), mn1 = fmaxf(m1, mx1);
        alpha0 = __expf(m0 - mn0);
        alpha1 = __expf(m1 - mn1);
        m0 = mn0;
        m1 = mn1;

        float rs0 = 0.f, rs1 = 0.f;
#pragma unroll
        for (int nt = 0; nt < 8; nt++) {
            S[nt][0] = __expf(S[nt][0] - m0);
            S[nt][1] = __expf(S[nt][1] - m0);
            S[nt][2] = __expf(S[nt][2] - m1);
            S[nt][3] = __expf(S[nt][3] - m1);
            rs0 += S[nt][0] + S[nt][1];
            rs1 += S[nt][2] + S[nt][3];
        }
        rs0 += __shfl_xor_sync(0xffffffffu, rs0, 1);
        rs0 += __shfl_xor_sync(0xffffffffu, rs0, 2);
        rs1 += __shfl_xor_sync(0xffffffffu, rs1, 1);
        rs1 += __shfl_xor_sync(0xffffffffu, rs1, 2);
        l0s = l0s * alpha0 + rs0;
        l1s = l1s * alpha1 + rs1;

        // ---- split P for the deferred PV next iteration
#pragma unroll
        for (int ks = 0; ks < 4; ks++) {
            split2(S[2 * ks][0],     S[2 * ks][1],     ph[ks][0], pl[ks][0]);
            split2(S[2 * ks][2],     S[2 * ks][3],     ph[ks][1], pl[ks][1]);
            split2(S[2 * ks + 1][0], S[2 * ks + 1][1], ph[ks][2], pl[ks][2]);
            split2(S[2 * ks + 1][2], S[2 * ks + 1][3], ph[ks][3], pl[ks][3]);
        }

        __syncthreads();   // all warps done reading K(nb) and V(nb-1)
        if (nb + 2 < NSEQ / 64) {
            issue_tile(h, nb + 2, smem_u32 + KBUF(nb & 1) * 4,
                       smem_u32 + VBUF((nb + 2) % 3) * 4);
        }
        cp_commit();
    }

    // ---- tail: PV of the last block
    {
        const uint32_t* VH = sm + VBUF((NSEQ / 64 - 1) % 3);
        const uint32_t* VL = VH + 2304;
#pragma unroll
        for (int nt = 0; nt < 8; nt++) {
            O[nt][0] *= alpha0;
            O[nt][1] *= alpha0;
            O[nt][2] *= alpha1;
            O[nt][3] *= alpha1;
        }
        pv_accum(O, ph, pl, VH, VL, g, q);
    }

    // ---- epilogue: normalize, split, write packed Hcat
    float inv0 = 1.0f / l0s, inv1 = 1.0f / l1s;
    const size_t r0 = (size_t)(bm * 128 + wid * 16 + g);
#pragma unroll
    for (int nt = 0; nt < 8; nt++) {
        int w = h * 32 + nt * 4 + q;
        uint32_t H, L;
        split2(O[nt][0] * inv0, O[nt][1] * inv0, H, L);
        g_HH[r0 * 256 + w] = H;
        g_HL[r0 * 256 + w] = L;
        split2(O[nt][2] * inv1, O[nt][3] * inv1, H, L);
        g_HH[(r0 + 8) * 256 + w] = H;
        g_HL[(r0 + 8) * 256 + w] = L;
    }
}

// ---------------- launcher --------------------------------------------------
extern "C" void kernel_launch(void* const* d_in, const int* in_sizes, int n_in,
                              void* d_out, int out_size) {
    const float* X   = (const float*)d_in[0];
    const int*   msk = (const int*)d_in[1];
    const float* WQ  = (const float*)d_in[2];
    const float* WK  = (const float*)d_in[3];
    const float* WV  = (const float*)d_in[4];
    const float* WO  = (const float*)d_in[5];
    float* out = (float*)d_out;

    cudaFuncSetAttribute(attn_kernel, cudaFuncAttributeMaxDynamicSharedMemorySize,
                         ATTN_SMEM_WORDS * 4);

    mask_pack<<<16384, 256>>>(msk);
    split_kernel<<<8192, 256>>>(X,  0, HNUM * NSEQ * FIN / 4);
    split_kernel<<<256,  256>>>(WQ, 1, HNUM * HD * FIN / 4);
    split_kernel<<<256,  256>>>(WK, 2, HNUM * HD * FIN / 4);
    split_kernel<<<256,  256>>>(WV, 3, HNUM * HD * FIN / 4);
    split_kernel<<<256,  256>>>(WO, 4, FIN * FIN / 4);

    qkv_kernel<<<dim3(NSEQ / 128, HNUM, 3), 256>>>();
    attn_kernel<<<dim3(NSEQ / 128, HNUM), 256, ATTN_SMEM_WORDS * 4>>>();
    out_kernel<<<dim3(NSEQ / 128, FIN / HD), 256>>>(out);
}

// round 4
// speedup vs baseline: 1.1893x; 1.1893x over previous
#include <cuda_runtime.h>
#include <cuda_bf16.h>
#include <cstdint>

#define HNUM 8
#define NSEQ 4096
#define FIN  512
#define HD   64

// ---------------- scratch (static device globals; no allocations) ----------
__device__ uint32_t g_XH[HNUM * NSEQ * (FIN / 2)];
__device__ uint32_t g_XL[HNUM * NSEQ * (FIN / 2)];
__device__ uint32_t g_WH[3 * HNUM * HD * (FIN / 2)];
__device__ uint32_t g_WL[3 * HNUM * HD * (FIN / 2)];
__device__ uint32_t g_WOH[FIN * (FIN / 2)];
__device__ uint32_t g_WOL[FIN * (FIN / 2)];
__device__ uint32_t g_QH[HNUM * NSEQ * (HD / 2)];
__device__ uint32_t g_QL[HNUM * NSEQ * (HD / 2)];
__device__ uint32_t g_KH[HNUM * NSEQ * (HD / 2)];
__device__ uint32_t g_KL[HNUM * NSEQ * (HD / 2)];
__device__ unsigned short g_VTH[HNUM * HD * NSEQ];
__device__ unsigned short g_VTL[HNUM * HD * NSEQ];
__device__ uint32_t g_HH[NSEQ * (FIN / 2)];
__device__ uint32_t g_HL[NSEQ * (FIN / 2)];

// ---------------- helpers --------------------------------------------------
__device__ __forceinline__ uint32_t pack_bf16x2(float lo_elem, float hi_elem) {
    return (uint32_t)__bfloat16_as_ushort(__float2bfloat16_rn(lo_elem)) |
           ((uint32_t)__bfloat16_as_ushort(__float2bfloat16_rn(hi_elem)) << 16);
}

__device__ __forceinline__ void split2(float a, float b, uint32_t& hi, uint32_t& lo) {
    float ah = __bfloat162float(__float2bfloat16_rn(a));
    float bh = __bfloat162float(__float2bfloat16_rn(b));
    hi = pack_bf16x2(a, b);
    lo = pack_bf16x2(a - ah, b - bh);
}

__device__ __forceinline__ void mma16816(float* c,
                                         uint32_t a0, uint32_t a1, uint32_t a2, uint32_t a3,
                                         uint32_t b0, uint32_t b1) {
    asm volatile(
        "mma.sync.aligned.m16n8k16.row.col.f32.bf16.bf16.f32 "
        "{%0,%1,%2,%3},{%4,%5,%6,%7},{%8,%9},{%0,%1,%2,%3};\n"
        : "+f"(c[0]), "+f"(c[1]), "+f"(c[2]), "+f"(c[3])
        : "r"(a0), "r"(a1), "r"(a2), "r"(a3), "r"(b0), "r"(b1));
}

__device__ __forceinline__ void ldsm4(uint32_t& r0, uint32_t& r1, uint32_t& r2,
                                      uint32_t& r3, uint32_t addr) {
    asm volatile("ldmatrix.sync.aligned.m8n8.x4.shared.b16 {%0,%1,%2,%3},[%4];"
                 : "=r"(r0), "=r"(r1), "=r"(r2), "=r"(r3) : "r"(addr));
}

__device__ __forceinline__ void cp16(uint32_t dst, const void* src) {
    asm volatile("cp.async.cg.shared.global [%0], [%1], 16;" :: "r"(dst), "l"(src));
}
__device__ __forceinline__ void cp_commit() {
    asm volatile("cp.async.commit_group;" ::: "memory");
}
__device__ __forceinline__ void cp_wait1() {
    asm volatile("cp.async.wait_group 1;" ::: "memory");
}
__device__ __forceinline__ void cp_wait0() {
    asm volatile("cp.async.wait_group 0;" ::: "memory");
}

#define NEG_BIG (-1.0e30f)

// ---------------- split kernel: fp32 -> packed bf16 hi/lo -------------------
__global__ void __launch_bounds__(256) split_kernel(const float* __restrict__ src,
                                                    int which, int nquads) {
    uint32_t* dH;
    uint32_t* dL;
    switch (which) {
        case 0: dH = g_XH;          dL = g_XL;          break;
        case 1: dH = g_WH;          dL = g_WL;          break;
        case 2: dH = g_WH + 131072; dL = g_WL + 131072; break;
        case 3: dH = g_WH + 262144; dL = g_WL + 262144; break;
        default: dH = g_WOH;        dL = g_WOL;         break;
    }
    for (int i = blockIdx.x * blockDim.x + threadIdx.x; i < nquads;
         i += gridDim.x * blockDim.x) {
        float4 v = reinterpret_cast<const float4*>(src)[i];
        uint32_t h0, l0, h1, l1;
        split2(v.x, v.y, h0, l0);
        split2(v.z, v.w, h1, l1);
        reinterpret_cast<uint2*>(dH)[i] = make_uint2(h0, h1);
        reinterpret_cast<uint2*>(dL)[i] = make_uint2(l0, l1);
    }
}

// ---------------- GEMM core: acc[128x64] += A[128,512] * B[64,512]^T --------
__device__ __forceinline__ void gemm_accum(const uint32_t* __restrict__ AHg,
                                           const uint32_t* __restrict__ ALg,
                                           const uint32_t* __restrict__ BHg,
                                           const uint32_t* __restrict__ BLg,
                                           float acc[8][4]) {
    __shared__ __align__(16) uint32_t AsH[128][36];
    __shared__ __align__(16) uint32_t AsL[128][36];
    __shared__ __align__(16) uint32_t BsH[64][36];
    __shared__ __align__(16) uint32_t BsL[64][36];

    const int tid = threadIdx.x;
    const int wid = tid >> 5, lane = tid & 31;
    const int g = lane >> 2, q = lane & 3;

    for (int kc = 0; kc < 256; kc += 32) {
#pragma unroll
        for (int j = 0; j < 4; j++) {
            int idx = tid + j * 256;
            int r = idx >> 3, c = (idx & 7) << 2;
            *reinterpret_cast<uint4*>(&AsH[r][c]) =
                *reinterpret_cast<const uint4*>(AHg + (size_t)r * 256 + kc + c);
            *reinterpret_cast<uint4*>(&AsL[r][c]) =
                *reinterpret_cast<const uint4*>(ALg + (size_t)r * 256 + kc + c);
        }
#pragma unroll
        for (int j = 0; j < 2; j++) {
            int idx = tid + j * 256;
            int r = idx >> 3, c = (idx & 7) << 2;
            *reinterpret_cast<uint4*>(&BsH[r][c]) =
                *reinterpret_cast<const uint4*>(BHg + (size_t)r * 256 + kc + c);
            *reinterpret_cast<uint4*>(&BsL[r][c]) =
                *reinterpret_cast<const uint4*>(BLg + (size_t)r * 256 + kc + c);
        }
        __syncthreads();
#pragma unroll
        for (int ks = 0; ks < 4; ks++) {
            const int ar = wid * 16 + g;
            const int wi = ks * 8 + q;
            uint32_t a0h = AsH[ar][wi],     a1h = AsH[ar + 8][wi];
            uint32_t a2h = AsH[ar][wi + 4], a3h = AsH[ar + 8][wi + 4];
            uint32_t a0l = AsL[ar][wi],     a1l = AsL[ar + 8][wi];
            uint32_t a2l = AsL[ar][wi + 4], a3l = AsL[ar + 8][wi + 4];
#pragma unroll
            for (int nt = 0; nt < 8; nt++) {
                const int br = nt * 8 + g;
                uint32_t b0h = BsH[br][wi], b1h = BsH[br][wi + 4];
                uint32_t b0l = BsL[br][wi], b1l = BsL[br][wi + 4];
                mma16816(acc[nt], a0h, a1h, a2h, a3h, b0h, b1h);
                mma16816(acc[nt], a0h, a1h, a2h, a3h, b0l, b1l);
                mma16816(acc[nt], a0l, a1l, a2l, a3l, b0h, b1h);
            }
        }
        __syncthreads();
    }
}

// ---------------- stage 1: QKV projections --------------------------------
__global__ void __launch_bounds__(256) qkv_kernel() {
    const int bm = blockIdx.x, h = blockIdx.y, z = blockIdx.z;
    const int tid = threadIdx.x;
    const int wid = tid >> 5, lane = tid & 31;
    const int g = lane >> 2, q = lane & 3;

    float acc[8][4];
#pragma unroll
    for (int i = 0; i < 8; i++)
#pragma unroll
        for (int j = 0; j < 4; j++) acc[i][j] = 0.f;

    const uint32_t* AH = g_XH + (size_t)(h * NSEQ + bm * 128) * 256;
    const uint32_t* AL = g_XL + (size_t)(h * NSEQ + bm * 128) * 256;
    const uint32_t* BH = g_WH + (size_t)((z * HNUM + h) * HD) * 256;
    const uint32_t* BL = g_WL + (size_t)((z * HNUM + h) * HD) * 256;
    gemm_accum(AH, AL, BH, BL, acc);

    const int r0 = wid * 16 + g;
    if (z < 2) {
        uint32_t* dH = (z == 0) ? g_QH : g_KH;
        uint32_t* dL = (z == 0) ? g_QL : g_KL;
        const size_t rb0 = (size_t)(h * NSEQ + bm * 128 + r0) * 32;
        const size_t rb1 = rb0 + 8 * 32;
#pragma unroll
        for (int nt = 0; nt < 8; nt++) {
            int w = nt * 4 + q;
            uint32_t H, L;
            split2(acc[nt][0], acc[nt][1], H, L);
            dH[rb0 + w] = H; dL[rb0 + w] = L;
            split2(acc[nt][2], acc[nt][3], H, L);
            dH[rb1 + w] = H; dL[rb1 + w] = L;
        }
    } else {
        const int n0 = bm * 128 + r0;
#pragma unroll
        for (int nt = 0; nt < 8; nt++) {
            int cx = nt * 8 + 2 * q;
#pragma unroll
            for (int e = 0; e < 2; e++) {
                size_t b0 = (size_t)(h * HD + cx + e) * NSEQ;
                float v0 = acc[nt][e], v1 = acc[nt][2 + e];
                float h0 = __bfloat162float(__float2bfloat16_rn(v0));
                float h1 = __bfloat162float(__float2bfloat16_rn(v1));
                g_VTH[b0 + n0]     = __bfloat16_as_ushort(__float2bfloat16_rn(v0));
                g_VTL[b0 + n0]     = __bfloat16_as_ushort(__float2bfloat16_rn(v0 - h0));
                g_VTH[b0 + n0 + 8] = __bfloat16_as_ushort(__float2bfloat16_rn(v1));
                g_VTL[b0 + n0 + 8] = __bfloat16_as_ushort(__float2bfloat16_rn(v1 - h1));
            }
        }
    }
}

// ---------------- stage 3: output projection ------------------------------
__global__ void __launch_bounds__(256) out_kernel(float* __restrict__ out) {
    const int bm = blockIdx.x, bn = blockIdx.y;
    const int tid = threadIdx.x;
    const int wid = tid >> 5, lane = tid & 31;
    const int g = lane >> 2, q = lane & 3;

    float acc[8][4];
#pragma unroll
    for (int i = 0; i < 8; i++)
#pragma unroll
        for (int j = 0; j < 4; j++) acc[i][j] = 0.f;

    gemm_accum(g_HH + (size_t)bm * 128 * 256, g_HL + (size_t)bm * 128 * 256,
               g_WOH + (size_t)bn * HD * 256, g_WOL + (size_t)bn * HD * 256, acc);

    const int r0 = wid * 16 + g;
#pragma unroll
    for (int nt = 0; nt < 8; nt++) {
        int cx = bn * HD + nt * 8 + 2 * q;
        *reinterpret_cast<float2*>(out + (size_t)(bm * 128 + r0) * FIN + cx) =
            make_float2(acc[nt][0], acc[nt][1]);
        *reinterpret_cast<float2*>(out + (size_t)(bm * 128 + r0 + 8) * FIN + cx) =
            make_float2(acc[nt][2], acc[nt][3]);
    }
}

// ---------------- stage 2: flash attention (BM=64, 128 threads) ------------
// double-buffered smem, per buffer 9216 words: KH@0, KL@2304, VTH@4608, VTL@6912
// row stride 36 words (32 data + 4 pad) -> ldmatrix rows hit distinct 16B banks
#define ATTN_BUF_WORDS 9216
#define ATTN_SMEM_BYTES (2 * ATTN_BUF_WORDS * 4)

__device__ __forceinline__ void issue_tile(int h, int nb, uint32_t sbase) {
    const int tid = threadIdx.x;
#pragma unroll
    for (int j = 0; j < 4; j++) {
        int chunk = tid + j * 128;
        int r = chunk >> 3, c = chunk & 7;
        const uint32_t* sKH = g_KH + (size_t)(h * NSEQ + nb * 64 + r) * 32 + c * 4;
        const uint32_t* sKL = g_KL + (size_t)(h * NSEQ + nb * 64 + r) * 32 + c * 4;
        const unsigned short* sVH = g_VTH + (size_t)(h * HD + r) * NSEQ + nb * 64 + c * 8;
        const unsigned short* sVL = g_VTL + (size_t)(h * HD + r) * NSEQ + nb * 64 + c * 8;
        uint32_t off = (uint32_t)(r * 36 + c * 4) * 4;
        cp16(sbase + off, sKH);
        cp16(sbase + off + 2304 * 4, sKL);
        cp16(sbase + off + 4608 * 4, sVH);
        cp16(sbase + off + 6912 * 4, sVL);
    }
}

__global__ void __launch_bounds__(128) attn_kernel(const int* __restrict__ mask) {
    extern __shared__ __align__(16) uint32_t sm[];
    const uint32_t smem_u32 = (uint32_t)__cvta_generic_to_shared(sm);

    const int tid = threadIdx.x, wid = tid >> 5, lane = tid & 31;
    const int g = lane >> 2, q = lane & 3;
    const int bm = blockIdx.x, h = blockIdx.y;

    // per-lane ldmatrix address component: matrix j = lane>>3, row-in-matrix = lane&7
    // word offset = (8*(j>>1) + row)*36 + (j&1)*4 ; scaled to bytes
    const int jm = lane >> 3, im = lane & 7;
    const uint32_t lwB = (uint32_t)(((8 * (jm >> 1) + im) * 36 + (jm & 1) * 4) * 4);

    // ---- Q fragments into registers (once per CTA): rows bm*64 + wid*16 ..
    uint32_t qh[4][4], ql[4][4];
    {
        const size_t rb0 = (size_t)(h * NSEQ + bm * 64 + wid * 16 + g) * 32;
        const size_t rb1 = rb0 + 8 * 32;
#pragma unroll
        for (int ks = 0; ks < 4; ks++) {
            int wi = ks * 8 + q;
            qh[ks][0] = g_QH[rb0 + wi];
            qh[ks][1] = g_QH[rb1 + wi];
            qh[ks][2] = g_QH[rb0 + wi + 4];
            qh[ks][3] = g_QH[rb1 + wi + 4];
            ql[ks][0] = g_QL[rb0 + wi];
            ql[ks][1] = g_QL[rb1 + wi];
            ql[ks][2] = g_QL[rb0 + wi + 4];
            ql[ks][3] = g_QL[rb1 + wi + 4];
        }
    }

    const int* mr0 = mask + ((size_t)h * NSEQ + (size_t)(bm * 64 + wid * 16 + g)) * NSEQ;
    const int* mr1 = mr0 + 8 * NSEQ;

    float O[8][4];
#pragma unroll
    for (int i = 0; i < 8; i++)
#pragma unroll
        for (int j = 0; j < 4; j++) O[i][j] = 0.f;
    const float NEGINF = __int_as_float(0xff800000);
    float m0 = NEGINF, m1 = NEGINF, l0s = 0.f, l1s = 0.f;

    issue_tile(h, 0, smem_u32);
    cp_commit();

    for (int nb = 0; nb < NSEQ / 64; nb++) {
        __syncthreads();   // previous buffer reads done
        if (nb + 1 < NSEQ / 64) {
            issue_tile(h, nb + 1, smem_u32 + ((nb + 1) & 1) * ATTN_BUF_WORDS * 4);
            cp_commit();
            cp_wait1();
        } else {
            cp_wait0();
        }
        __syncthreads();

        const uint32_t kaddr  = smem_u32 + (uint32_t)((nb & 1) * ATTN_BUF_WORDS) * 4;
        const uint32_t kaddrL = kaddr + 2304 * 4;
        const uint32_t vaddr  = kaddr + 4608 * 4;
        const uint32_t vaddrL = kaddr + 6912 * 4;

        // ---- S = Q * K^T  via ldmatrix.x4 fragment loads
        float S[8][4];
#pragma unroll
        for (int i = 0; i < 8; i++)
#pragma unroll
            for (int j = 0; j < 4; j++) S[i][j] = 0.f;
#pragma unroll
        for (int ks = 0; ks < 4; ks++) {
#pragma unroll
            for (int p = 0; p < 4; p++) {
                uint32_t off = (uint32_t)((p * 576 + ks * 8) * 4) + lwB;
                uint32_t h0, h1, h2, h3, l0, l1, l2, l3;
                ldsm4(h0, h1, h2, h3, kaddr + off);
                ldsm4(l0, l1, l2, l3, kaddrL + off);
                mma16816(S[2 * p],     qh[ks][0], qh[ks][1], qh[ks][2], qh[ks][3], h0, h1);
                mma16816(S[2 * p],     qh[ks][0], qh[ks][1], qh[ks][2], qh[ks][3], l0, l1);
                mma16816(S[2 * p],     ql[ks][0], ql[ks][1], ql[ks][2], ql[ks][3], h0, h1);
                mma16816(S[2 * p + 1], qh[ks][0], qh[ks][1], qh[ks][2], qh[ks][3], h2, h3);
                mma16816(S[2 * p + 1], qh[ks][0], qh[ks][1], qh[ks][2], qh[ks][3], l2, l3);
                mma16816(S[2 * p + 1], ql[ks][0], ql[ks][1], ql[ks][2], ql[ks][3], h2, h3);
            }
        }

        // ---- scale + mask (direct from gmem)
#pragma unroll
        for (int nt = 0; nt < 8; nt++) {
            int2 ma = *reinterpret_cast<const int2*>(mr0 + nb * 64 + nt * 8 + 2 * q);
            int2 mb = *reinterpret_cast<const int2*>(mr1 + nb * 64 + nt * 8 + 2 * q);
            S[nt][0] = ma.x ? S[nt][0] * 0.125f : NEG_BIG;
            S[nt][1] = ma.y ? S[nt][1] * 0.125f : NEG_BIG;
            S[nt][2] = mb.x ? S[nt][2] * 0.125f : NEG_BIG;
            S[nt][3] = mb.y ? S[nt][3] * 0.125f : NEG_BIG;
        }

        // ---- online softmax
        float mx0 = S[0][0], mx1 = S[0][2];
#pragma unroll
        for (int nt = 0; nt < 8; nt++) {
            mx0 = fmaxf(mx0, fmaxf(S[nt][0], S[nt][1]));
            mx1 = fmaxf(mx1, fmaxf(S[nt][2], S[nt][3]));
        }
        mx0 = fmaxf(mx0, __shfl_xor_sync(0xffffffffu, mx0, 1));
        mx0 = fmaxf(mx0, __shfl_xor_sync(0xffffffffu, mx0, 2));
        mx1 = fmaxf(mx1, __shfl_xor_sync(0xffffffffu, mx1, 1));
        mx1 = fmaxf(mx1, __shfl_xor_sync(0xffffffffu, mx1, 2));

        float mn0 = fmaxf(m0, mx0), mn1 = fmaxf(m1, mx1);
        float al0 = __expf(m0 - mn0), al1 = __expf(m1 - mn1);
        m0 = mn0;
        m1 = mn1;

        float rs0 = 0.f, rs1 = 0.f;
#pragma unroll
        for (int nt = 0; nt < 8; nt++) {
            S[nt][0] = __expf(S[nt][0] - m0);
            S[nt][1] = __expf(S[nt][1] - m0);
            S[nt][2] = __expf(S[nt][2] - m1);
            S[nt][3] = __expf(S[nt][3] - m1);
            rs0 += S[nt][0] + S[nt][1];
            rs1 += S[nt][2] + S[nt][3];
        }
        rs0 += __shfl_xor_sync(0xffffffffu, rs0, 1);
        rs0 += __shfl_xor_sync(0xffffffffu, rs0, 2);
        rs1 += __shfl_xor_sync(0xffffffffu, rs1, 1);
        rs1 += __shfl_xor_sync(0xffffffffu, rs1, 2);
        l0s = l0s * al0 + rs0;
        l1s = l1s * al1 + rs1;
#pragma unroll
        for (int nt = 0; nt < 8; nt++) {
            O[nt][0] *= al0;
            O[nt][1] *= al0;
            O[nt][2] *= al1;
            O[nt][3] *= al1;
        }

        // ---- O += P * V  via ldmatrix.x4 on V^T tile
#pragma unroll
        for (int ks = 0; ks < 4; ks++) {
            uint32_t a0h, a0l, a1h, a1l, a2h, a2l, a3h, a3l;
            split2(S[2 * ks][0],     S[2 * ks][1],     a0h, a0l);
            split2(S[2 * ks][2],     S[2 * ks][3],     a1h, a1l);
            split2(S[2 * ks + 1][0], S[2 * ks + 1][1], a2h, a2l);
            split2(S[2 * ks + 1][2], S[2 * ks + 1][3], a3h, a3l);
#pragma unroll
            for (int p = 0; p < 4; p++) {
                uint32_t off = (uint32_t)((p * 576 + ks * 8) * 4) + lwB;
                uint32_t h0, h1, h2, h3, l0, l1, l2, l3;
                ldsm4(h0, h1, h2, h3, vaddr + off);
                ldsm4(l0, l1, l2, l3, vaddrL + off);
                mma16816(O[2 * p],     a0h, a1h, a2h, a3h, h0, h1);
                mma16816(O[2 * p],     a0h, a1h, a2h, a3h, l0, l1);
                mma16816(O[2 * p],     a0l, a1l, a2l, a3l, h0, h1);
                mma16816(O[2 * p + 1], a0h, a1h, a2h, a3h, h2, h3);
                mma16816(O[2 * p + 1], a0h, a1h, a2h, a3h, l2, l3);
                mma16816(O[2 * p + 1], a0l, a1l, a2l, a3l, h2, h3);
            }
        }
    }

    // ---- epilogue: normalize, split, write packed Hcat
    float inv0 = 1.0f / l0s, inv1 = 1.0f / l1s;
    const size_t r0 = (size_t)(bm * 64 + wid * 16 + g);
#pragma unroll
    for (int nt = 0; nt < 8; nt++) {
        int w = h * 32 + nt * 4 + q;
        uint32_t H, L;
        split2(O[nt][0] * inv0, O[nt][1] * inv0, H, L);
        g_HH[r0 * 256 + w] = H;
        g_HL[r0 * 256 + w] = L;
        split2(O[nt][2] * inv1, O[nt][3] * inv1, H, L);
        g_HH[(r0 + 8) * 256 + w] = H;
        g_HL[(r0 + 8) * 256 + w] = L;
    }
}

// ---------------- launcher --------------------------------------------------
extern "C" void kernel_launch(void* const* d_in, const int* in_sizes, int n_in,
                              void* d_out, int out_size) {
    const float* X   = (const float*)d_in[0];
    const int*   msk = (const int*)d_in[1];
    const float* WQ  = (const float*)d_in[2];
    const float* WK  = (const float*)d_in[3];
    const float* WV  = (const float*)d_in[4];
    const float* WO  = (const float*)d_in[5];
    float* out = (float*)d_out;

    cudaFuncSetAttribute(attn_kernel, cudaFuncAttributeMaxDynamicSharedMemorySize,
                         ATTN_SMEM_BYTES);

    split_kernel<<<8192, 256>>>(X,  0, HNUM * NSEQ * FIN / 4);
    split_kernel<<<256,  256>>>(WQ, 1, HNUM * HD * FIN / 4);
    split_kernel<<<256,  256>>>(WK, 2, HNUM * HD * FIN / 4);
    split_kernel<<<256,  256>>>(WV, 3, HNUM * HD * FIN / 4);
    split_kernel<<<256,  256>>>(WO, 4, FIN * FIN / 4);

    qkv_kernel<<<dim3(NSEQ / 128, HNUM, 3), 256>>>();
    attn_kernel<<<dim3(NSEQ / 64, HNUM), 128, ATTN_SMEM_BYTES>>>(msk);
    out_kernel<<<dim3(NSEQ / 128, FIN / HD), 256>>>(out);
}

// round 5
// speedup vs baseline: 1.2393x; 1.0420x over previous
#include <cuda_runtime.h>
#include <cuda_bf16.h>
#include <cstdint>

#define HNUM 8
#define NSEQ 4096
#define FIN  512
#define HD   64

// ---------------- scratch (static device globals; no allocations) ----------
__device__ uint32_t g_WH[3 * HNUM * HD * (FIN / 2)];
__device__ uint32_t g_WL[3 * HNUM * HD * (FIN / 2)];
__device__ uint32_t g_WOH[FIN * (FIN / 2)];
__device__ uint32_t g_WOL[FIN * (FIN / 2)];
__device__ uint32_t g_QH[HNUM * NSEQ * (HD / 2)];
__device__ uint32_t g_QL[HNUM * NSEQ * (HD / 2)];
__device__ uint32_t g_KH[HNUM * NSEQ * (HD / 2)];
__device__ uint32_t g_KL[HNUM * NSEQ * (HD / 2)];
__device__ unsigned short g_VTH[HNUM * HD * NSEQ];
__device__ unsigned short g_VTL[HNUM * HD * NSEQ];
__device__ uint32_t g_HH[NSEQ * (FIN / 2)];
__device__ uint32_t g_HL[NSEQ * (FIN / 2)];

// ---------------- helpers --------------------------------------------------
__device__ __forceinline__ uint32_t pack_bf16x2(float lo_elem, float hi_elem) {
    return (uint32_t)__bfloat16_as_ushort(__float2bfloat16_rn(lo_elem)) |
           ((uint32_t)__bfloat16_as_ushort(__float2bfloat16_rn(hi_elem)) << 16);
}

__device__ __forceinline__ void split2(float a, float b, uint32_t& hi, uint32_t& lo) {
    float ah = __bfloat162float(__float2bfloat16_rn(a));
    float bh = __bfloat162float(__float2bfloat16_rn(b));
    hi = pack_bf16x2(a, b);
    lo = pack_bf16x2(a - ah, b - bh);
}

__device__ __forceinline__ void mma16816(float* c,
                                         uint32_t a0, uint32_t a1, uint32_t a2, uint32_t a3,
                                         uint32_t b0, uint32_t b1) {
    asm volatile(
        "mma.sync.aligned.m16n8k16.row.col.f32.bf16.bf16.f32 "
        "{%0,%1,%2,%3},{%4,%5,%6,%7},{%8,%9},{%0,%1,%2,%3};\n"
        : "+f"(c[0]), "+f"(c[1]), "+f"(c[2]), "+f"(c[3])
        : "r"(a0), "r"(a1), "r"(a2), "r"(a3), "r"(b0), "r"(b1));
}

__device__ __forceinline__ void ldsm4(uint32_t& r0, uint32_t& r1, uint32_t& r2,
                                      uint32_t& r3, uint32_t addr) {
    asm volatile("ldmatrix.sync.aligned.m8n8.x4.shared.b16 {%0,%1,%2,%3},[%4];"
                 : "=r"(r0), "=r"(r1), "=r"(r2), "=r"(r3) : "r"(addr));
}

__device__ __forceinline__ void cp16(uint32_t dst, const void* src) {
    asm volatile("cp.async.cg.shared.global [%0], [%1], 16;" :: "r"(dst), "l"(src));
}
__device__ __forceinline__ void cp_commit() {
    asm volatile("cp.async.commit_group;" ::: "memory");
}
__device__ __forceinline__ void cp_wait1() {
    asm volatile("cp.async.wait_group 1;" ::: "memory");
}
__device__ __forceinline__ void cp_wait0() {
    asm volatile("cp.async.wait_group 0;" ::: "memory");
}
__device__ __forceinline__ void prefetchL2(const void* p) {
    asm volatile("prefetch.global.L2 [%0];" :: "l"(p));
}

#define NEG_BIG (-1.0e30f)
#define SCALE2  0.18033688f   /* 0.125 * log2(e) */

// ---------------- split kernel: fp32 -> packed bf16 hi/lo (weights) ---------
__global__ void __launch_bounds__(256) split_kernel(const float* __restrict__ src,
                                                    int which, int nquads) {
    uint32_t* dH;
    uint32_t* dL;
    switch (which) {
        case 1: dH = g_WH;          dL = g_WL;          break;
        case 2: dH = g_WH + 131072; dL = g_WL + 131072; break;
        case 3: dH = g_WH + 262144; dL = g_WL + 262144; break;
        default: dH = g_WOH;        dL = g_WOL;         break;
    }
    for (int i = blockIdx.x * blockDim.x + threadIdx.x; i < nquads;
         i += gridDim.x * blockDim.x) {
        float4 v = reinterpret_cast<const float4*>(src)[i];
        uint32_t h0, l0, h1, l1;
        split2(v.x, v.y, h0, l0);
        split2(v.z, v.w, h1, l1);
        reinterpret_cast<uint2*>(dH)[i] = make_uint2(h0, h1);
        reinterpret_cast<uint2*>(dL)[i] = make_uint2(l0, l1);
    }
}

// ---------------- stage 1: fused QKV projection -----------------------------
// BM=64 rows, 128 threads. dyn smem words:
//   AsH@0 [64][36], AsL@2304, BsH[z]@4608+z*2304, BsL[z]@11520+z*2304
#define QKV_SMEM_WORDS 18432

__global__ void __launch_bounds__(128, 3) qkv_fused(const float* __restrict__ X) {
    extern __shared__ __align__(16) uint32_t qs[];
    const uint32_t sbase = (uint32_t)__cvta_generic_to_shared(qs);
    const int tid = threadIdx.x, wid = tid >> 5, lane = tid & 31;
    const int g = lane >> 2, q = lane & 3;
    const int bm = blockIdx.x, h = blockIdx.y;

    const int jm = lane >> 3, im = lane & 7;
    const uint32_t lwB = (uint32_t)(((8 * (jm >> 1) + im) * 36 + (jm & 1) * 4) * 4);
    const uint32_t lwA = (uint32_t)(((lane & 15) * 36 + (lane >> 4) * 4) * 4);

    float acc[3][8][4];
#pragma unroll
    for (int z = 0; z < 3; z++)
#pragma unroll
        for (int i = 0; i < 8; i++)
#pragma unroll
            for (int j = 0; j < 4; j++) acc[z][i][j] = 0.f;

    const float* Xbase = X + ((size_t)h * NSEQ + (size_t)bm * 64) * FIN;

    for (int kc = 0; kc < 8; kc++) {
        // A: 64 rows x 64 floats, split in-kernel
#pragma unroll
        for (int j = 0; j < 8; j++) {
            int idx = tid + j * 128;               // 0..1023 float4
            int r = idx >> 4, c4 = (idx & 15) << 2;
            float4 v = *reinterpret_cast<const float4*>(Xbase + (size_t)r * FIN + kc * 64 + c4);
            uint32_t h0, l0, h1, l1;
            split2(v.x, v.y, h0, l0);
            split2(v.z, v.w, h1, l1);
            *reinterpret_cast<uint2*>(&qs[r * 36 + (c4 >> 1)]) = make_uint2(h0, h1);
            *reinterpret_cast<uint2*>(&qs[2304 + r * 36 + (c4 >> 1)]) = make_uint2(l0, l1);
        }
        // B: 3 x 64 rows x 32 words (pre-split)
#pragma unroll
        for (int z = 0; z < 3; z++) {
            const uint32_t* BH = g_WH + ((size_t)(z * HNUM + h) * HD) * 256 + kc * 32;
            const uint32_t* BL = g_WL + ((size_t)(z * HNUM + h) * HD) * 256 + kc * 32;
#pragma unroll
            for (int j = 0; j < 4; j++) {
                int idx = tid + j * 128;           // 0..511 uint4
                int r = idx >> 3, c = (idx & 7) << 2;
                *reinterpret_cast<uint4*>(&qs[4608 + z * 2304 + r * 36 + c]) =
                    *reinterpret_cast<const uint4*>(BH + (size_t)r * 256 + c);
                *reinterpret_cast<uint4*>(&qs[11520 + z * 2304 + r * 36 + c]) =
                    *reinterpret_cast<const uint4*>(BL + (size_t)r * 256 + c);
            }
        }
        __syncthreads();
#pragma unroll
        for (int ks = 0; ks < 4; ks++) {
            uint32_t a0h, a1h, a2h, a3h, a0l, a1l, a2l, a3l;
            uint32_t aoff = sbase + (uint32_t)((wid * 16 * 36 + ks * 8) * 4) + lwA;
            ldsm4(a0h, a1h, a2h, a3h, aoff);
            ldsm4(a0l, a1l, a2l, a3l, aoff + 2304 * 4);
#pragma unroll
            for (int z = 0; z < 3; z++) {
                uint32_t bbase = sbase + (uint32_t)((4608 + z * 2304) * 4);
#pragma unroll
                for (int p = 0; p < 4; p++) {
                    uint32_t off = bbase + (uint32_t)((p * 576 + ks * 8) * 4) + lwB;
                    uint32_t b0, b1, b2, b3, c0, c1, c2, c3;
                    ldsm4(b0, b1, b2, b3, off);
                    ldsm4(c0, c1, c2, c3, off + 6912 * 4);
                    mma16816(acc[z][2 * p],     a0h, a1h, a2h, a3h, b0, b1);
                    mma16816(acc[z][2 * p],     a0h, a1h, a2h, a3h, c0, c1);
                    mma16816(acc[z][2 * p],     a0l, a1l, a2l, a3l, b0, b1);
                    mma16816(acc[z][2 * p + 1], a0h, a1h, a2h, a3h, b2, b3);
                    mma16816(acc[z][2 * p + 1], a0h, a1h, a2h, a3h, c2, c3);
                    mma16816(acc[z][2 * p + 1], a0l, a1l, a2l, a3l, b2, b3);
                }
            }
        }
        __syncthreads();
    }

    // ---- epilogue
    const int r0 = wid * 16 + g;
#pragma unroll
    for (int z = 0; z < 2; z++) {
        uint32_t* dH = (z == 0) ? g_QH : g_KH;
        uint32_t* dL = (z == 0) ? g_QL : g_KL;
        const size_t rb0 = (size_t)(h * NSEQ + bm * 64 + r0) * 32;
        const size_t rb1 = rb0 + 8 * 32;
#pragma unroll
        for (int nt = 0; nt < 8; nt++) {
            int w = nt * 4 + q;
            uint32_t H, L;
            split2(acc[z][nt][0], acc[z][nt][1], H, L);
            dH[rb0 + w] = H; dL[rb0 + w] = L;
            split2(acc[z][nt][2], acc[z][nt][3], H, L);
            dH[rb1 + w] = H; dL[rb1 + w] = L;
        }
    }
    {
        const int n0 = bm * 64 + r0;
#pragma unroll
        for (int nt = 0; nt < 8; nt++) {
            int cx = nt * 8 + 2 * q;
#pragma unroll
            for (int e = 0; e < 2; e++) {
                size_t b0 = (size_t)(h * HD + cx + e) * NSEQ;
                float v0 = acc[2][nt][e], v1 = acc[2][nt][2 + e];
                float h0 = __bfloat162float(__float2bfloat16_rn(v0));
                float h1 = __bfloat162float(__float2bfloat16_rn(v1));
                g_VTH[b0 + n0]     = __bfloat16_as_ushort(__float2bfloat16_rn(v0));
                g_VTL[b0 + n0]     = __bfloat16_as_ushort(__float2bfloat16_rn(v0 - h0));
                g_VTH[b0 + n0 + 8] = __bfloat16_as_ushort(__float2bfloat16_rn(v1));
                g_VTL[b0 + n0 + 8] = __bfloat16_as_ushort(__float2bfloat16_rn(v1 - h1));
            }
        }
    }
}

// ---------------- stage 3: output projection ------------------------------
__device__ __forceinline__ void gemm_accum(const uint32_t* __restrict__ AHg,
                                           const uint32_t* __restrict__ ALg,
                                           const uint32_t* __restrict__ BHg,
                                           const uint32_t* __restrict__ BLg,
                                           float acc[8][4]) {
    __shared__ __align__(16) uint32_t AsH[128][36];
    __shared__ __align__(16) uint32_t AsL[128][36];
    __shared__ __align__(16) uint32_t BsH[64][36];
    __shared__ __align__(16) uint32_t BsL[64][36];

    const int tid = threadIdx.x;
    const int wid = tid >> 5, lane = tid & 31;
    const int g = lane >> 2, q = lane & 3;

    for (int kc = 0; kc < 256; kc += 32) {
#pragma unroll
        for (int j = 0; j < 4; j++) {
            int idx = tid + j * 256;
            int r = idx >> 3, c = (idx & 7) << 2;
            *reinterpret_cast<uint4*>(&AsH[r][c]) =
                *reinterpret_cast<const uint4*>(AHg + (size_t)r * 256 + kc + c);
            *reinterpret_cast<uint4*>(&AsL[r][c]) =
                *reinterpret_cast<const uint4*>(ALg + (size_t)r * 256 + kc + c);
        }
#pragma unroll
        for (int j = 0; j < 2; j++) {
            int idx = tid + j * 256;
            int r = idx >> 3, c = (idx & 7) << 2;
            *reinterpret_cast<uint4*>(&BsH[r][c]) =
                *reinterpret_cast<const uint4*>(BHg + (size_t)r * 256 + kc + c);
            *reinterpret_cast<uint4*>(&BsL[r][c]) =
                *reinterpret_cast<const uint4*>(BLg + (size_t)r * 256 + kc + c);
        }
        __syncthreads();
#pragma unroll
        for (int ks = 0; ks < 4; ks++) {
            const int ar = wid * 16 + g;
            const int wi = ks * 8 + q;
            uint32_t a0h = AsH[ar][wi],     a1h = AsH[ar + 8][wi];
            uint32_t a2h = AsH[ar][wi + 4], a3h = AsH[ar + 8][wi + 4];
            uint32_t a0l = AsL[ar][wi],     a1l = AsL[ar + 8][wi];
            uint32_t a2l = AsL[ar][wi + 4], a3l = AsL[ar + 8][wi + 4];
#pragma unroll
            for (int nt = 0; nt < 8; nt++) {
                const int br = nt * 8 + g;
                uint32_t b0h = BsH[br][wi], b1h = BsH[br][wi + 4];
                uint32_t b0l = BsL[br][wi], b1l = BsL[br][wi + 4];
                mma16816(acc[nt], a0h, a1h, a2h, a3h, b0h, b1h);
                mma16816(acc[nt], a0h, a1h, a2h, a3h, b0l, b1l);
                mma16816(acc[nt], a0l, a1l, a2l, a3l, b0h, b1h);
            }
        }
        __syncthreads();
    }
}

__global__ void __launch_bounds__(256) out_kernel(float* __restrict__ out) {
    const int bm = blockIdx.x, bn = blockIdx.y;
    const int tid = threadIdx.x;
    const int wid = tid >> 5, lane = tid & 31;
    const int g = lane >> 2, q = lane & 3;

    float acc[8][4];
#pragma unroll
    for (int i = 0; i < 8; i++)
#pragma unroll
        for (int j = 0; j < 4; j++) acc[i][j] = 0.f;

    gemm_accum(g_HH + (size_t)bm * 128 * 256, g_HL + (size_t)bm * 128 * 256,
               g_WOH + (size_t)bn * HD * 256, g_WOL + (size_t)bn * HD * 256, acc);

    const int r0 = wid * 16 + g;
#pragma unroll
    for (int nt = 0; nt < 8; nt++) {
        int cx = bn * HD + nt * 8 + 2 * q;
        *reinterpret_cast<float2*>(out + (size_t)(bm * 128 + r0) * FIN + cx) =
            make_float2(acc[nt][0], acc[nt][1]);
        *reinterpret_cast<float2*>(out + (size_t)(bm * 128 + r0 + 8) * FIN + cx) =
            make_float2(acc[nt][2], acc[nt][3]);
    }
}

// ---------------- stage 2: flash attention (BM=64, 128 threads) ------------
#define ATTN_BUF_WORDS 9216
#define ATTN_SMEM_BYTES (2 * ATTN_BUF_WORDS * 4)

__device__ __forceinline__ void issue_tile(int h, int nb, uint32_t sbase) {
    const int tid = threadIdx.x;
#pragma unroll
    for (int j = 0; j < 4; j++) {
        int chunk = tid + j * 128;
        int r = chunk >> 3, c = chunk & 7;
        const uint32_t* sKH = g_KH + (size_t)(h * NSEQ + nb * 64 + r) * 32 + c * 4;
        const uint32_t* sKL = g_KL + (size_t)(h * NSEQ + nb * 64 + r) * 32 + c * 4;
        const unsigned short* sVH = g_VTH + (size_t)(h * HD + r) * NSEQ + nb * 64 + c * 8;
        const unsigned short* sVL = g_VTL + (size_t)(h * HD + r) * NSEQ + nb * 64 + c * 8;
        uint32_t off = (uint32_t)(r * 36 + c * 4) * 4;
        cp16(sbase + off, sKH);
        cp16(sbase + off + 2304 * 4, sKL);
        cp16(sbase + off + 4608 * 4, sVH);
        cp16(sbase + off + 6912 * 4, sVL);
    }
}

__global__ void __launch_bounds__(128) attn_kernel(const int* __restrict__ mask) {
    extern __shared__ __align__(16) uint32_t sm[];
    const uint32_t smem_u32 = (uint32_t)__cvta_generic_to_shared(sm);

    const int tid = threadIdx.x, wid = tid >> 5, lane = tid & 31;
    const int g = lane >> 2, q = lane & 3;
    const int bm = blockIdx.x, h = blockIdx.y;

    const int jm = lane >> 3, im = lane & 7;
    const uint32_t lwB = (uint32_t)(((8 * (jm >> 1) + im) * 36 + (jm & 1) * 4) * 4);

    uint32_t qh[4][4], ql[4][4];
    {
        const size_t rb0 = (size_t)(h * NSEQ + bm * 64 + wid * 16 + g) * 32;
        const size_t rb1 = rb0 + 8 * 32;
#pragma unroll
        for (int ks = 0; ks < 4; ks++) {
            int wi = ks * 8 + q;
            qh[ks][0] = g_QH[rb0 + wi];
            qh[ks][1] = g_QH[rb1 + wi];
            qh[ks][2] = g_QH[rb0 + wi + 4];
            qh[ks][3] = g_QH[rb1 + wi + 4];
            ql[ks][0] = g_QL[rb0 + wi];
            ql[ks][1] = g_QL[rb1 + wi];
            ql[ks][2] = g_QL[rb0 + wi + 4];
            ql[ks][3] = g_QL[rb1 + wi + 4];
        }
    }

    const int* mr0 = mask + ((size_t)h * NSEQ + (size_t)(bm * 64 + wid * 16 + g)) * NSEQ;
    const int* mr1 = mr0 + 8 * NSEQ;

    float O[8][4];
#pragma unroll
    for (int i = 0; i < 8; i++)
#pragma unroll
        for (int j = 0; j < 4; j++) O[i][j] = 0.f;
    const float NEGINF = __int_as_float(0xff800000);
    float m0 = NEGINF, m1 = NEGINF, l0s = 0.f, l1s = 0.f;

    // prefetch first mask tile
    prefetchL2(mr0);
    prefetchL2(mr0 + 32);
    prefetchL2(mr1);
    prefetchL2(mr1 + 32);

    issue_tile(h, 0, smem_u32);
    cp_commit();

    for (int nb = 0; nb < NSEQ / 64; nb++) {
        // prefetch next mask tile into L2 (hidden behind this iteration)
        if (nb + 1 < NSEQ / 64) {
            const int* p0 = mr0 + (nb + 1) * 64;
            const int* p1 = mr1 + (nb + 1) * 64;
            prefetchL2(p0);
            prefetchL2(p0 + 32);
            prefetchL2(p1);
            prefetchL2(p1 + 32);
        }

        __syncthreads();
        if (nb + 1 < NSEQ / 64) {
            issue_tile(h, nb + 1, smem_u32 + ((nb + 1) & 1) * ATTN_BUF_WORDS * 4);
            cp_commit();
            cp_wait1();
        } else {
            cp_wait0();
        }
        __syncthreads();

        const uint32_t kaddr  = smem_u32 + (uint32_t)((nb & 1) * ATTN_BUF_WORDS) * 4;
        const uint32_t kaddrL = kaddr + 2304 * 4;
        const uint32_t vaddr  = kaddr + 4608 * 4;
        const uint32_t vaddrL = kaddr + 6912 * 4;

        // ---- S = Q * K^T
        float S[8][4];
#pragma unroll
        for (int i = 0; i < 8; i++)
#pragma unroll
            for (int j = 0; j < 4; j++) S[i][j] = 0.f;
#pragma unroll
        for (int ks = 0; ks < 4; ks++) {
#pragma unroll
            for (int p = 0; p < 4; p++) {
                uint32_t off = (uint32_t)((p * 576 + ks * 8) * 4) + lwB;
                uint32_t h0, h1, h2, h3, l0, l1, l2, l3;
                ldsm4(h0, h1, h2, h3, kaddr + off);
                ldsm4(l0, l1, l2, l3, kaddrL + off);
                mma16816(S[2 * p],     qh[ks][0], qh[ks][1], qh[ks][2], qh[ks][3], h0, h1);
                mma16816(S[2 * p],     qh[ks][0], qh[ks][1], qh[ks][2], qh[ks][3], l0, l1);
                mma16816(S[2 * p],     ql[ks][0], ql[ks][1], ql[ks][2], ql[ks][3], h0, h1);
                mma16816(S[2 * p + 1], qh[ks][0], qh[ks][1], qh[ks][2], qh[ks][3], h2, h3);
                mma16816(S[2 * p + 1], qh[ks][0], qh[ks][1], qh[ks][2], qh[ks][3], l2, l3);
                mma16816(S[2 * p + 1], ql[ks][0], ql[ks][1], ql[ks][2], ql[ks][3], h2, h3);
            }
        }

        // ---- mask + fold (0.125*log2e) for exp2-domain softmax
#pragma unroll
        for (int nt = 0; nt < 8; nt++) {
            int2 ma = *reinterpret_cast<const int2*>(mr0 + nb * 64 + nt * 8 + 2 * q);
            int2 mb = *reinterpret_cast<const int2*>(mr1 + nb * 64 + nt * 8 + 2 * q);
            S[nt][0] = ma.x ? S[nt][0] * SCALE2 : NEG_BIG;
            S[nt][1] = ma.y ? S[nt][1] * SCALE2 : NEG_BIG;
            S[nt][2] = mb.x ? S[nt][2] * SCALE2 : NEG_BIG;
            S[nt][3] = mb.y ? S[nt][3] * SCALE2 : NEG_BIG;
        }

        // ---- online softmax (log2 domain)
        float mx0 = S[0][0], mx1 = S[0][2];
#pragma unroll
        for (int nt = 0; nt < 8; nt++) {
            mx0 = fmaxf(mx0, fmaxf(S[nt][0], S[nt][1]));
            mx1 = fmaxf(mx1, fmaxf(S[nt][2], S[nt][3]));
        }
        mx0 = fmaxf(mx0, __shfl_xor_sync(0xffffffffu, mx0, 1));
        mx0 = fmaxf(mx0, __shfl_xor_sync(0xffffffffu, mx0, 2));
        mx1 = fmaxf(mx1, __shfl_xor_sync(0xffffffffu, mx1, 1));
        mx1 = fmaxf(mx1, __shfl_xor_sync(0xffffffffu, mx1, 2));

        float mn0 = fmaxf(m0, mx0), mn1 = fmaxf(m1, mx1);
        float al0 = exp2f(m0 - mn0), al1 = exp2f(m1 - mn1);
        m0 = mn0;
        m1 = mn1;

        float rs0 = 0.f, rs1 = 0.f;
#pragma unroll
        for (int nt = 0; nt < 8; nt++) {
            S[nt][0] = exp2f(S[nt][0] - m0);
            S[nt][1] = exp2f(S[nt][1] - m0);
            S[nt][2] = exp2f(S[nt][2] - m1);
            S[nt][3] = exp2f(S[nt][3] - m1);
            rs0 += S[nt][0] + S[nt][1];
            rs1 += S[nt][2] + S[nt][3];
        }
        rs0 += __shfl_xor_sync(0xffffffffu, rs0, 1);
        rs0 += __shfl_xor_sync(0xffffffffu, rs0, 2);
        rs1 += __shfl_xor_sync(0xffffffffu, rs1, 1);
        rs1 += __shfl_xor_sync(0xffffffffu, rs1, 2);
        l0s = l0s * al0 + rs0;
        l1s = l1s * al1 + rs1;
#pragma unroll
        for (int nt = 0; nt < 8; nt++) {
            O[nt][0] *= al0;
            O[nt][1] *= al0;
            O[nt][2] *= al1;
            O[nt][3] *= al1;
        }

        // ---- O += P * V
#pragma unroll
        for (int ks = 0; ks < 4; ks++) {
            uint32_t a0h, a0l, a1h, a1l, a2h, a2l, a3h, a3l;
            split2(S[2 * ks][0],     S[2 * ks][1],     a0h, a0l);
            split2(S[2 * ks][2],     S[2 * ks][3],     a1h, a1l);
            split2(S[2 * ks + 1][0], S[2 * ks + 1][1], a2h, a2l);
            split2(S[2 * ks + 1][2], S[2 * ks + 1][3], a3h, a3l);
#pragma unroll
            for (int p = 0; p < 4; p++) {
                uint32_t off = (uint32_t)((p * 576 + ks * 8) * 4) + lwB;
                uint32_t h0, h1, h2, h3, l0, l1, l2, l3;
                ldsm4(h0, h1, h2, h3, vaddr + off);
                ldsm4(l0, l1, l2, l3, vaddrL + off);
                mma16816(O[2 * p],     a0h, a1h, a2h, a3h, h0, h1);
                mma16816(O[2 * p],     a0h, a1h, a2h, a3h, l0, l1);
                mma16816(O[2 * p],     a0l, a1l, a2l, a3l, h0, h1);
                mma16816(O[2 * p + 1], a0h, a1h, a2h, a3h, h2, h3);
                mma16816(O[2 * p + 1], a0h, a1h, a2h, a3h, l2, l3);
                mma16816(O[2 * p + 1], a0l, a1l, a2l, a3l, h2, h3);
            }
        }
    }

    // ---- epilogue
    float inv0 = 1.0f / l0s, inv1 = 1.0f / l1s;
    const size_t r0 = (size_t)(bm * 64 + wid * 16 + g);
#pragma unroll
    for (int nt = 0; nt < 8; nt++) {
        int w = h * 32 + nt * 4 + q;
        uint32_t H, L;
        split2(O[nt][0] * inv0, O[nt][1] * inv0, H, L);
        g_HH[r0 * 256 + w] = H;
        g_HL[r0 * 256 + w] = L;
        split2(O[nt][2] * inv1, O[nt][3] * inv1, H, L);
        g_HH[(r0 + 8) * 256 + w] = H;
        g_HL[(r0 + 8) * 256 + w] = L;
    }
}

// ---------------- launcher --------------------------------------------------
extern "C" void kernel_launch(void* const* d_in, const int* in_sizes, int n_in,
                              void* d_out, int out_size) {
    const float* X   = (const float*)d_in[0];
    const int*   msk = (const int*)d_in[1];
    const float* WQ  = (const float*)d_in[2];
    const float* WK  = (const float*)d_in[3];
    const float* WV  = (const float*)d_in[4];
    const float* WO  = (const float*)d_in[5];
    float* out = (float*)d_out;

    cudaFuncSetAttribute(attn_kernel, cudaFuncAttributeMaxDynamicSharedMemorySize,
                         ATTN_SMEM_BYTES);
    cudaFuncSetAttribute(qkv_fused, cudaFuncAttributeMaxDynamicSharedMemorySize,
                         QKV_SMEM_WORDS * 4);

    split_kernel<<<256, 256>>>(WQ, 1, HNUM * HD * FIN / 4);
    split_kernel<<<256, 256>>>(WK, 2, HNUM * HD * FIN / 4);
    split_kernel<<<256, 256>>>(WV, 3, HNUM * HD * FIN / 4);
    split_kernel<<<256, 256>>>(WO, 4, FIN * FIN / 4);

    qkv_fused<<<dim3(NSEQ / 64, HNUM), 128, QKV_SMEM_WORDS * 4>>>(X);
    attn_kernel<<<dim3(NSEQ / 64, HNUM), 128, ATTN_SMEM_BYTES>>>(msk);
    out_kernel<<<dim3(NSEQ / 128, FIN / HD), 256>>>(out);
}